// round 1
// baseline (speedup 1.0000x reference)
#include <cuda_runtime.h>
#include <math.h>

#define BATCH 8
#define SEQ   4096
#define DIM   1024
#define VOCAB 50257
#define CHUNK  64
#define NCHUNK 64   /* CHUNK*NCHUNK == SEQ */

// Scratch (allocation-free rule: __device__ globals)
__device__ float g_hpart[NCHUNK * BATCH * DIM];  // per-chunk EMA partials (2 MB)
__device__ float g_h [BATCH * DIM];
__device__ float g_Hc[BATCH * DIM];
__device__ float g_Vp[BATCH * DIM];

__device__ __forceinline__ float sigmoidf_(float x) { return 1.0f / (1.0f + expf(-x)); }

// ---------------------------------------------------------------------------
// Kernel A: EMA as truncated geometric weighted sum, chunked backward in time.
// grid = (NCHUNK, BATCH), block = 256 threads; thread t handles channels 4t..4t+3.
// Chunk j covers k in [j*CHUNK, (j+1)*CHUNK) where k = steps back from t = S-1.
// Skip the whole chunk for this thread if d^{k0} < 1e-7 for all 4 channels
// (remaining weight mass from this chunk onward is exactly d^{k0} <= 1e-7).
// ---------------------------------------------------------------------------
__global__ __launch_bounds__(256) void ema_chunk_kernel(
    const int*   __restrict__ ids,
    const float* __restrict__ emb,
    const float* __restrict__ enc_decay)
{
    const int chunk = blockIdx.x;
    const int b     = blockIdx.y;
    const int t4    = threadIdx.x;            // float4 group of channels

    __shared__ int sids[CHUNK];
    if (threadIdx.x < CHUNK) {
        int k = chunk * CHUNK + threadIdx.x;
        sids[threadIdx.x] = ids[b * SEQ + (SEQ - 1 - k)];
    }

    float4 ed = ((const float4*)enc_decay)[t4];
    float dx = sigmoidf_(ed.x);
    float dy = sigmoidf_(ed.y);
    float dz = sigmoidf_(ed.z);
    float dw = sigmoidf_(ed.w);

    float fk0 = (float)(chunk * CHUNK);
    float px = powf(dx, fk0);
    float py = powf(dy, fk0);
    float pz = powf(dz, fk0);
    float pw = powf(dw, fk0);

    __syncthreads();

    float4 acc = make_float4(0.f, 0.f, 0.f, 0.f);
    float pmax = fmaxf(fmaxf(px, py), fmaxf(pz, pw));
    if (pmax > 1e-7f) {
        float wx = (1.0f - dx) * px;
        float wy = (1.0f - dy) * py;
        float wz = (1.0f - dz) * pz;
        float ww = (1.0f - dw) * pw;
        #pragma unroll 8
        for (int i = 0; i < CHUNK; i++) {
            const float4 x = __ldg((const float4*)emb + (size_t)sids[i] * (DIM / 4) + t4);
            acc.x += wx * x.x;  acc.y += wy * x.y;
            acc.z += wz * x.z;  acc.w += ww * x.w;
            wx *= dx; wy *= dy; wz *= dz; ww *= dw;
        }
    }
    ((float4*)g_hpart)[((size_t)chunk * BATCH + b) * (DIM / 4) + t4] = acc;
}

// ---------------------------------------------------------------------------
// Kernel R: deterministic fixed-order reduction of chunk partials -> g_h
// ---------------------------------------------------------------------------
__global__ __launch_bounds__(256) void reduce_h_kernel()
{
    int e = blockIdx.x * 256 + threadIdx.x;   // 0..2047 (float4 index over BATCH*DIM)
    const float4* hp = (const float4*)g_hpart;
    float4 s = make_float4(0.f, 0.f, 0.f, 0.f);
    #pragma unroll 8
    for (int c = 0; c < NCHUNK; c++) {
        float4 v = hp[(size_t)c * (BATCH * DIM / 4) + e];
        s.x += v.x; s.y += v.y; s.z += v.z; s.w += v.w;
    }
    ((float4*)g_h)[e] = s;
}

// ---------------------------------------------------------------------------
// Kernel B: small dense (8 x 1024 x 1024) with fused epilogue.
// MODE 0: in = tanh(g_h) (=V), out: g_Hc = sigmoid(cry_decay)*h + sigmoid(V@Wg^T+bg)*V
// MODE 1: in = g_Hc,            out: g_Vp = tanh(Hc@Wc^T + bc)
// grid = 32 blocks (32 outputs each), 256 threads = 8 warps, 4 outputs/warp.
// ---------------------------------------------------------------------------
template <int MODE>
__global__ __launch_bounds__(256) void dense_kernel(
    const float* __restrict__ W,
    const float* __restrict__ bias,
    const float* __restrict__ cry_decay)
{
    __shared__ __align__(16) float sh[BATCH * DIM];   // 32 KB input activations
    for (int e = threadIdx.x; e < BATCH * DIM; e += 256)
        sh[e] = (MODE == 0) ? tanhf(g_h[e]) : g_Hc[e];
    __syncthreads();

    const int wid  = threadIdx.x >> 5;
    const int lane = threadIdx.x & 31;
    const int o0   = blockIdx.x * 32;
    const float4* sh4 = (const float4*)sh;

    for (int q = 0; q < 4; q++) {
        const int o = o0 + wid * 4 + q;
        float acc[BATCH];
        #pragma unroll
        for (int b = 0; b < BATCH; b++) acc[b] = 0.f;

        const float4* Wrow = (const float4*)W + (size_t)o * (DIM / 4);
        #pragma unroll
        for (int i = 0; i < 8; i++) {
            float4 w4 = __ldg(Wrow + i * 32 + lane);
            #pragma unroll
            for (int b = 0; b < BATCH; b++) {
                float4 v4 = sh4[b * 256 + i * 32 + lane];
                acc[b] += w4.x * v4.x + w4.y * v4.y + w4.z * v4.z + w4.w * v4.w;
            }
        }
        #pragma unroll
        for (int b = 0; b < BATCH; b++)
            #pragma unroll
            for (int off = 16; off; off >>= 1)
                acc[b] += __shfl_xor_sync(0xffffffffu, acc[b], off);

        if (lane < BATCH) {
            const int b = lane;
            float dot = acc[b] + bias[o];
            if (MODE == 0) {
                float g  = sigmoidf_(dot);
                float cd = sigmoidf_(cry_decay[o]);
                g_Hc[b * DIM + o] = cd * g_h[b * DIM + o] + g * sh[b * DIM + o];
            } else {
                g_Vp[b * DIM + o] = tanhf(dot);
            }
        }
    }
}

// ---------------------------------------------------------------------------
// Kernel C: decoder  logits[b,v] = Vp[b,:] . dec_W[v,:] + dec_b[v]
// warp handles 4 vocab rows; dec_W streamed as coalesced float4; Vp in shared.
// Memory-bound: 206 MB of dec_W read once.
// ---------------------------------------------------------------------------
__global__ __launch_bounds__(256) void decoder_kernel(
    const float* __restrict__ dec_W,
    const float* __restrict__ dec_b,
    float*       __restrict__ out)
{
    __shared__ __align__(16) float sh[BATCH * DIM];
    for (int e = threadIdx.x; e < BATCH * DIM; e += 256)
        sh[e] = g_Vp[e];
    __syncthreads();

    const int wid  = threadIdx.x >> 5;
    const int lane = threadIdx.x & 31;
    const int v0   = (blockIdx.x * 8 + wid) * 4;
    if (v0 >= VOCAB) return;   // uniform per warp

    int vr[4];
    #pragma unroll
    for (int r = 0; r < 4; r++) vr[r] = min(v0 + r, VOCAB - 1);

    float acc[4][BATCH];
    #pragma unroll
    for (int r = 0; r < 4; r++)
        #pragma unroll
        for (int b = 0; b < BATCH; b++) acc[r][b] = 0.f;

    const float4* W4  = (const float4*)dec_W;
    const float4* sh4 = (const float4*)sh;

    #pragma unroll
    for (int i = 0; i < 8; i++) {
        float4 w4[4];
        #pragma unroll
        for (int r = 0; r < 4; r++)
            w4[r] = __ldg(W4 + (size_t)vr[r] * 256 + i * 32 + lane);
        #pragma unroll
        for (int b = 0; b < BATCH; b++) {
            float4 v4 = sh4[b * 256 + i * 32 + lane];
            #pragma unroll
            for (int r = 0; r < 4; r++)
                acc[r][b] += w4[r].x * v4.x + w4[r].y * v4.y
                           + w4[r].z * v4.z + w4[r].w * v4.w;
        }
    }

    #pragma unroll
    for (int r = 0; r < 4; r++)
        #pragma unroll
        for (int b = 0; b < BATCH; b++)
            #pragma unroll
            for (int off = 16; off; off >>= 1)
                acc[r][b] += __shfl_xor_sync(0xffffffffu, acc[r][b], off);

    if (lane < BATCH) {
        const int b = lane;
        #pragma unroll
        for (int r = 0; r < 4; r++) {
            int v = v0 + r;
            if (v < VOCAB)
                out[(size_t)b * VOCAB + v] = acc[r][b] + dec_b[v];
        }
    }
}

// ---------------------------------------------------------------------------
extern "C" void kernel_launch(void* const* d_in, const int* in_sizes, int n_in,
                              void* d_out, int out_size)
{
    (void)in_sizes; (void)n_in; (void)out_size;
    const int*   ids = (const int*)  d_in[0];
    const float* emb = (const float*)d_in[1];
    const float* enc = (const float*)d_in[2];
    const float* cry = (const float*)d_in[3];
    const float* gW  = (const float*)d_in[4];
    const float* gb  = (const float*)d_in[5];
    const float* cW  = (const float*)d_in[6];
    const float* cb  = (const float*)d_in[7];
    const float* dW  = (const float*)d_in[8];
    const float* db  = (const float*)d_in[9];
    float* out = (float*)d_out;

    ema_chunk_kernel<<<dim3(NCHUNK, BATCH), 256>>>(ids, emb, enc);
    reduce_h_kernel<<<(BATCH * DIM / 4) / 256, 256>>>();
    dense_kernel<0><<<DIM / 32, 256>>>(gW, gb, cry);
    dense_kernel<1><<<DIM / 32, 256>>>(cW, cb, nullptr);
    decoder_kernel<<<(VOCAB + 31) / 32, 256>>>(dW, db, out);
}

// round 2
// speedup vs baseline: 1.2853x; 1.2853x over previous
#include <cuda_runtime.h>
#include <math.h>

#define BATCH 8
#define SEQ   4096
#define DIM   1024
#define VOCAB 50257
#define CHUNK  64
#define NCHUNK 64   /* CHUNK*NCHUNK == SEQ */

// Scratch (allocation-free rule: __device__ globals)
__device__ float g_hpart[NCHUNK * BATCH * DIM];  // per-chunk EMA partials (2 MB)
__device__ float g_h [BATCH * DIM];
__device__ float g_Hc[BATCH * DIM];
__device__ float g_Vp[BATCH * DIM];

__device__ __forceinline__ float sigmoidf_(float x) { return 1.0f / (1.0f + expf(-x)); }

// Packed dual-FP32 FMA (Blackwell): acc.{lo,hi} += w.{lo,hi} * v.{lo,hi}
__device__ __forceinline__ void ffma2(unsigned long long& a,
                                      unsigned long long w,
                                      unsigned long long v)
{
    asm("fma.rn.f32x2 %0, %1, %2, %0;" : "+l"(a) : "l"(w), "l"(v));
}
__device__ __forceinline__ float unpack_sum(unsigned long long a)
{
    float lo, hi;
    asm("mov.b64 {%0, %1}, %2;" : "=f"(lo), "=f"(hi) : "l"(a));
    return lo + hi;
}

// ---------------------------------------------------------------------------
// Kernel A: EMA as truncated geometric weighted sum, chunked backward in time.
// ---------------------------------------------------------------------------
__global__ __launch_bounds__(256) void ema_chunk_kernel(
    const int*   __restrict__ ids,
    const float* __restrict__ emb,
    const float* __restrict__ enc_decay)
{
    const int chunk = blockIdx.x;
    const int b     = blockIdx.y;
    const int t4    = threadIdx.x;            // float4 group of channels

    __shared__ int sids[CHUNK];
    if (threadIdx.x < CHUNK) {
        int k = chunk * CHUNK + threadIdx.x;
        sids[threadIdx.x] = ids[b * SEQ + (SEQ - 1 - k)];
    }

    float4 ed = ((const float4*)enc_decay)[t4];
    float dx = sigmoidf_(ed.x);
    float dy = sigmoidf_(ed.y);
    float dz = sigmoidf_(ed.z);
    float dw = sigmoidf_(ed.w);

    float fk0 = (float)(chunk * CHUNK);
    float px = powf(dx, fk0);
    float py = powf(dy, fk0);
    float pz = powf(dz, fk0);
    float pw = powf(dw, fk0);

    __syncthreads();

    float4 acc = make_float4(0.f, 0.f, 0.f, 0.f);
    float pmax = fmaxf(fmaxf(px, py), fmaxf(pz, pw));
    if (pmax > 1e-7f) {
        float wx = (1.0f - dx) * px;
        float wy = (1.0f - dy) * py;
        float wz = (1.0f - dz) * pz;
        float ww = (1.0f - dw) * pw;
        #pragma unroll 8
        for (int i = 0; i < CHUNK; i++) {
            const float4 x = __ldg((const float4*)emb + (size_t)sids[i] * (DIM / 4) + t4);
            acc.x += wx * x.x;  acc.y += wy * x.y;
            acc.z += wz * x.z;  acc.w += ww * x.w;
            wx *= dx; wy *= dy; wz *= dz; ww *= dw;
        }
    }
    ((float4*)g_hpart)[((size_t)chunk * BATCH + b) * (DIM / 4) + t4] = acc;
}

// ---------------------------------------------------------------------------
// Kernel R: deterministic fixed-order reduction of chunk partials -> g_h
// ---------------------------------------------------------------------------
__global__ __launch_bounds__(256) void reduce_h_kernel()
{
    int e = blockIdx.x * 256 + threadIdx.x;   // float4 index over BATCH*DIM
    const float4* hp = (const float4*)g_hpart;
    float4 s = make_float4(0.f, 0.f, 0.f, 0.f);
    #pragma unroll 8
    for (int c = 0; c < NCHUNK; c++) {
        float4 v = hp[(size_t)c * (BATCH * DIM / 4) + e];
        s.x += v.x; s.y += v.y; s.z += v.z; s.w += v.w;
    }
    ((float4*)g_h)[e] = s;
}

// ---------------------------------------------------------------------------
// Kernel B: small dense (8 x 1024 x 1024), warp-per-output, 128 blocks.
// MODE 0: in = tanh(g_h) (=V), out: g_Hc = sigmoid(cry_decay)*h + sigmoid(V@Wg^T+bg)*V
// MODE 1: in = g_Hc,            out: g_Vp = tanh(Hc@Wc^T + bc)
// ---------------------------------------------------------------------------
template <int MODE>
__global__ __launch_bounds__(256) void dense_kernel(
    const float* __restrict__ W,
    const float* __restrict__ bias,
    const float* __restrict__ cry_decay)
{
    __shared__ __align__(16) float sh[BATCH * DIM];   // 32 KB input activations
    for (int e = threadIdx.x; e < BATCH * DIM; e += 256)
        sh[e] = (MODE == 0) ? tanhf(g_h[e]) : g_Hc[e];
    __syncthreads();

    const int wid  = threadIdx.x >> 5;
    const int lane = threadIdx.x & 31;
    const int o    = blockIdx.x * 8 + wid;            // one output per warp
    const float4* sh4 = (const float4*)sh;

    float acc[BATCH];
    #pragma unroll
    for (int b = 0; b < BATCH; b++) acc[b] = 0.f;

    const float4* Wrow = (const float4*)W + (size_t)o * (DIM / 4);
    #pragma unroll
    for (int i = 0; i < 8; i++) {
        float4 w4 = __ldg(Wrow + i * 32 + lane);
        #pragma unroll
        for (int b = 0; b < BATCH; b++) {
            float4 v4 = sh4[b * 256 + i * 32 + lane];
            acc[b] += w4.x * v4.x + w4.y * v4.y + w4.z * v4.z + w4.w * v4.w;
        }
    }
    #pragma unroll
    for (int b = 0; b < BATCH; b++)
        #pragma unroll
        for (int off = 16; off; off >>= 1)
            acc[b] += __shfl_xor_sync(0xffffffffu, acc[b], off);

    if (lane < BATCH) {
        const int b = lane;
        float dot = acc[b] + bias[o];
        if (MODE == 0) {
            float g  = sigmoidf_(dot);
            float cd = sigmoidf_(cry_decay[o]);
            g_Hc[b * DIM + o] = cd * g_h[b * DIM + o] + g * sh[b * DIM + o];
        } else {
            g_Vp[b * DIM + o] = tanhf(dot);
        }
    }
}

// ---------------------------------------------------------------------------
// Kernel C: decoder  logits[b,v] = Vp[b,:] . dec_W[v,:] + dec_b[v]
// Warp handles 4 vocab rows; K paired into f32x2 packed FMAs (halves FMA
// instruction count -> memory-bound). dec_W streamed as LDG.128; Vp in smem.
// ---------------------------------------------------------------------------
__global__ __launch_bounds__(256, 2) void decoder_kernel(
    const float* __restrict__ dec_W,
    const float* __restrict__ dec_b,
    float*       __restrict__ out)
{
    __shared__ __align__(16) float sh[BATCH * DIM];
    for (int e = threadIdx.x; e < BATCH * DIM; e += 256)
        sh[e] = g_Vp[e];
    __syncthreads();

    const int wid  = threadIdx.x >> 5;
    const int lane = threadIdx.x & 31;
    const int v0   = (blockIdx.x * 8 + wid) * 4;
    if (v0 >= VOCAB) return;   // uniform per warp; no further barriers below

    int vr[4];
    #pragma unroll
    for (int r = 0; r < 4; r++) vr[r] = min(v0 + r, VOCAB - 1);

    unsigned long long acc[4][BATCH];
    #pragma unroll
    for (int r = 0; r < 4; r++)
        #pragma unroll
        for (int b = 0; b < BATCH; b++) acc[r][b] = 0ull;

    const ulonglong2* W2  = (const ulonglong2*)dec_W;   // 256 ull2 per row
    const ulonglong2* sh2 = (const ulonglong2*)sh;

    #pragma unroll
    for (int i = 0; i < 8; i++) {
        ulonglong2 w2[4];
        #pragma unroll
        for (int r = 0; r < 4; r++)
            w2[r] = __ldg(W2 + (size_t)vr[r] * 256 + i * 32 + lane);
        #pragma unroll
        for (int b = 0; b < BATCH; b++) {
            ulonglong2 v2 = sh2[b * 256 + i * 32 + lane];
            #pragma unroll
            for (int r = 0; r < 4; r++) {
                ffma2(acc[r][b], w2[r].x, v2.x);
                ffma2(acc[r][b], w2[r].y, v2.y);
            }
        }
    }

    float accf[4][BATCH];
    #pragma unroll
    for (int r = 0; r < 4; r++)
        #pragma unroll
        for (int b = 0; b < BATCH; b++) {
            float s = unpack_sum(acc[r][b]);
            #pragma unroll
            for (int off = 16; off; off >>= 1)
                s += __shfl_xor_sync(0xffffffffu, s, off);
            accf[r][b] = s;
        }

    if (lane < BATCH) {
        const int b = lane;
        #pragma unroll
        for (int r = 0; r < 4; r++) {
            int v = v0 + r;
            if (v < VOCAB)
                out[(size_t)b * VOCAB + v] = accf[r][b] + dec_b[v];
        }
    }
}

// ---------------------------------------------------------------------------
extern "C" void kernel_launch(void* const* d_in, const int* in_sizes, int n_in,
                              void* d_out, int out_size)
{
    (void)in_sizes; (void)n_in; (void)out_size;
    const int*   ids = (const int*)  d_in[0];
    const float* emb = (const float*)d_in[1];
    const float* enc = (const float*)d_in[2];
    const float* cry = (const float*)d_in[3];
    const float* gW  = (const float*)d_in[4];
    const float* gb  = (const float*)d_in[5];
    const float* cW  = (const float*)d_in[6];
    const float* cb  = (const float*)d_in[7];
    const float* dW  = (const float*)d_in[8];
    const float* db  = (const float*)d_in[9];
    float* out = (float*)d_out;

    ema_chunk_kernel<<<dim3(NCHUNK, BATCH), 256>>>(ids, emb, enc);
    reduce_h_kernel<<<(BATCH * DIM / 4) / 256, 256>>>();
    dense_kernel<0><<<DIM / 8, 256>>>(gW, gb, cry);
    dense_kernel<1><<<DIM / 8, 256>>>(cW, cb, nullptr);
    decoder_kernel<<<(VOCAB + 31) / 32, 256>>>(dW, db, out);
}